// round 5
// baseline (speedup 1.0000x reference)
#include <cuda_runtime.h>
#include <cuda_bf16.h>
#include <math.h>

// Problem constants (fixed by the reference)
#define NN 20000
#define EE 640000
#define GG 128
#define H1 128
#define H2 128
#define RR 8
#define KAGG (RR * GG)   // 1024

// ---------------- scratch (device globals; device-code use only) -----------
__device__ float g_cnt[NN * RR];
__device__ float g_agg[(size_t)NN * KAGG]; // ~82MB
__device__ float g_h[NN * H1];
__device__ float g_q[NN * H2];
__device__ float g_k[NN * H2];
__device__ float g_v[NN * H2];
__device__ float g_e[EE];
__device__ float g_den[NN];

// ---------------- fused zero kernel ----------------------------------------
__global__ void zero_kernel() {
    size_t i = ((size_t)blockIdx.x * blockDim.x + threadIdx.x) * 4;
    size_t n = (size_t)NN * KAGG;
    if (i + 3 < n) *(float4*)(&g_agg[i]) = make_float4(0.f, 0.f, 0.f, 0.f);
    size_t j = (size_t)blockIdx.x * blockDim.x + threadIdx.x;
    if (j < NN * RR) g_cnt[j] = 0.f;
    if (j < NN) g_den[j] = 0.f;
}

// ---------------- edge counting --------------------------------------------
__global__ void count_kernel(const int* __restrict__ dst,
                             const int* __restrict__ etype) {
    int e = blockIdx.x * blockDim.x + threadIdx.x;
    if (e >= EE) return;
    atomicAdd(&g_cnt[dst[e] * RR + etype[e]], 1.0f);
}

// ---------------- RGCN scatter: agg[dst, rel] += x[src]/cnt ----------------
__global__ void scatter_rgcn_kernel(const int* __restrict__ src,
                                    const int* __restrict__ dst,
                                    const int* __restrict__ etype,
                                    const float* __restrict__ x) {
    int e = blockIdx.x * 8 + (threadIdx.x >> 5);
    if (e >= EE) return;
    int lane = threadIdx.x & 31;
    int s = src[e], d = dst[e], r = etype[e];
    float inv = 1.0f / fmaxf(g_cnt[d * RR + r], 1.0f);
    float4 xv = *(const float4*)&x[(size_t)s * GG + lane * 4];
    float* ag = g_agg + (size_t)d * KAGG + r * GG + lane * 4;
    atomicAdd(ag + 0, xv.x * inv);
    atomicAdd(ag + 1, xv.y * inv);
    atomicAdd(ag + 2, xv.z * inv);
    atomicAdd(ag + 3, xv.w * inv);
}

// ---------------- 64x128x16 double-buffered GEMM core -----------------------
// 256 threads, microtile 4x8. As[buf][k][row] transposed, Bs[buf][k][col].
struct Smem {
    float As[2][16][64];
    float Bs[2][16][128];
};

// One K-segment with software pipeline. Assumes K % 16 == 0, K >= 16.
__device__ __forceinline__ void mm_seg_db(const float* __restrict__ A, int lda, int K,
                                          const float* __restrict__ B,
                                          Smem* sm, int row0, int M,
                                          float acc[4][8], int& buf) {
    int tid = threadIdx.x;
    int tx = tid & 15, ty = tid >> 4;

    // A-load mapping: 64x16 = 256 float4; thread t -> row=t>>2, kc=(t&3)*4
    int ar = tid >> 2;
    int akc = (tid & 3) * 4;
    int agr = row0 + ar;
    const float* aptr = (agr < M) ? &A[(size_t)agr * lda + akc] : nullptr;
    // B-load mapping: 16x128 = 512 float4; 2 per thread
    int bk0 = tid >> 5;              // 0..7
    int bc0 = (tid & 31) * 4;
    int bk1 = bk0 + 8;               // 8..15

    // prologue: load slab 0 into buf
    __syncthreads();  // protect previous segment's reads of this buffer
    {
        float4 va = aptr ? *(const float4*)aptr : make_float4(0.f,0.f,0.f,0.f);
        float4 vb0 = *(const float4*)&B[(size_t)bk0 * 128 + bc0];
        float4 vb1 = *(const float4*)&B[(size_t)bk1 * 128 + bc0];
        sm->As[buf][akc+0][ar] = va.x; sm->As[buf][akc+1][ar] = va.y;
        sm->As[buf][akc+2][ar] = va.z; sm->As[buf][akc+3][ar] = va.w;
        *(float4*)&sm->Bs[buf][bk0][bc0] = vb0;
        *(float4*)&sm->Bs[buf][bk1][bc0] = vb1;
    }
    __syncthreads();

    for (int k0 = 0; k0 < K; k0 += 16) {
        int nxt = k0 + 16;
        float4 va, vb0, vb1;
        if (nxt < K) {
            va = aptr ? *(const float4*)(aptr + nxt) : make_float4(0.f,0.f,0.f,0.f);
            vb0 = *(const float4*)&B[(size_t)(nxt + bk0) * 128 + bc0];
            vb1 = *(const float4*)&B[(size_t)(nxt + bk1) * 128 + bc0];
        }
        // compute on current buffer
        #pragma unroll
        for (int kk = 0; kk < 16; kk++) {
            float4 pa = *(float4*)&sm->As[buf][kk][ty * 4];
            float4 q0 = *(float4*)&sm->Bs[buf][kk][tx * 8];
            float4 q1 = *(float4*)&sm->Bs[buf][kk][tx * 8 + 4];
            float av[4] = {pa.x, pa.y, pa.z, pa.w};
            float bv[8] = {q0.x,q0.y,q0.z,q0.w,q1.x,q1.y,q1.z,q1.w};
            #pragma unroll
            for (int i = 0; i < 4; i++)
                #pragma unroll
                for (int j = 0; j < 8; j++) acc[i][j] += av[i] * bv[j];
        }
        if (nxt < K) {
            int nb = buf ^ 1;
            sm->As[nb][akc+0][ar] = va.x; sm->As[nb][akc+1][ar] = va.y;
            sm->As[nb][akc+2][ar] = va.z; sm->As[nb][akc+3][ar] = va.w;
            *(float4*)&sm->Bs[nb][bk0][bc0] = vb0;
            *(float4*)&sm->Bs[nb][bk1][bc0] = vb1;
            __syncthreads();
            buf = nb;
        }
    }
}

__device__ __forceinline__ void mm_epilogue64(float* __restrict__ C,
                                              const float* __restrict__ bias,
                                              int row0, int M, float acc[4][8],
                                              int do_relu) {
    int tid = threadIdx.x;
    int tx = tid & 15, ty = tid >> 4;
    #pragma unroll
    for (int i = 0; i < 4; i++) {
        int gr = row0 + ty * 4 + i;
        if (gr >= M) continue;
        #pragma unroll
        for (int j = 0; j < 8; j++) {
            int c = tx * 8 + j;
            float vv = acc[i][j] + bias[c];
            if (do_relu) vv = fmaxf(vv, 0.f);
            C[(size_t)gr * 128 + c] = vv;
        }
    }
}

// h = relu(agg @ W_stack + x @ root + bias)
__global__ void __launch_bounds__(256)
gemm_h_kernel(const float* __restrict__ x,
              const float* __restrict__ W,      // [1024,128]
              const float* __restrict__ root,   // [128,128]
              const float* __restrict__ bias) {
    __shared__ Smem sm;
    float acc[4][8];
    #pragma unroll
    for (int i = 0; i < 4; i++)
        #pragma unroll
        for (int j = 0; j < 8; j++) acc[i][j] = 0.f;
    int row0 = blockIdx.x * 64;
    int buf = 0;
    mm_seg_db(g_agg, KAGG, KAGG, W, &sm, row0, NN, acc, buf);
    mm_seg_db(x, GG, GG, root, &sm, row0, NN, acc, buf);
    mm_epilogue64(g_h, bias, row0, NN, acc, 1);
}

// q/k/v/skip in one launch: blockIdx.y selects the matrix
__global__ void __launch_bounds__(256)
gemm_qkvs_kernel(const float* __restrict__ Wq, const float* __restrict__ bq,
                 const float* __restrict__ Wk, const float* __restrict__ bk,
                 const float* __restrict__ Wv, const float* __restrict__ bv,
                 const float* __restrict__ Ws, const float* __restrict__ bs,
                 float* __restrict__ out) {
    const float* B; const float* bias; float* C;
    switch (blockIdx.y) {
        case 0:  B = Wq; bias = bq; C = g_q; break;
        case 1:  B = Wk; bias = bk; C = g_k; break;
        case 2:  B = Wv; bias = bv; C = g_v; break;
        default: B = Ws; bias = bs; C = out; break;
    }
    __shared__ Smem sm;
    float acc[4][8];
    #pragma unroll
    for (int i = 0; i < 4; i++)
        #pragma unroll
        for (int j = 0; j < 8; j++) acc[i][j] = 0.f;
    int row0 = blockIdx.x * 64;
    int buf = 0;
    mm_seg_db(g_h, H1, H1, B, &sm, row0, NN, acc, buf);
    mm_epilogue64(C, bias, row0, NN, acc, 0);
}

// ---------------- fused score + exp + denominator ---------------------------
// No max-subtraction: |score| ~ O(6) << 88, exp cannot overflow, and
// alpha = e/sum(e) is mathematically identical to the max-shifted form.
__global__ void score_exp_kernel(const int* __restrict__ src,
                                 const int* __restrict__ dst) {
    int e = blockIdx.x * 8 + (threadIdx.x >> 5);
    if (e >= EE) return;
    int lane = threadIdx.x & 31;
    int s = src[e], d = dst[e];
    float4 qv = *(const float4*)&g_q[(size_t)d * H2 + lane * 4];
    float4 kv = *(const float4*)&g_k[(size_t)s * H2 + lane * 4];
    float acc = qv.x * kv.x + qv.y * kv.y + qv.z * kv.z + qv.w * kv.w;
    #pragma unroll
    for (int o = 16; o; o >>= 1) acc += __shfl_xor_sync(0xFFFFFFFFu, acc, o);
    if (lane == 0) {
        float ex = __expf(acc * 0.08838834764831845f);  // 1/sqrt(128)
        g_e[e] = ex;
        atomicAdd(&g_den[d], ex);
    }
}

// ---------------- weighted V scatter ----------------------------------------
__global__ void scatter_v_kernel(const int* __restrict__ src,
                                 const int* __restrict__ dst,
                                 float* __restrict__ out) {
    int e = blockIdx.x * 8 + (threadIdx.x >> 5);
    if (e >= EE) return;
    int lane = threadIdx.x & 31;
    int s = src[e], d = dst[e];
    float alpha = g_e[e] / fmaxf(g_den[d], 1e-16f);
    float4 vv = *(const float4*)&g_v[(size_t)s * H2 + lane * 4];
    float* od = out + (size_t)d * H2 + lane * 4;
    atomicAdd(od + 0, alpha * vv.x);
    atomicAdd(od + 1, alpha * vv.y);
    atomicAdd(od + 2, alpha * vv.z);
    atomicAdd(od + 3, alpha * vv.w);
}

// ---------------- final relu in place ---------------------------------------
__global__ void relu_kernel(float* __restrict__ out, int n) {
    int i = blockIdx.x * blockDim.x + threadIdx.x;
    if (i < n) out[i] = fmaxf(out[i], 0.f);
}

// ---------------------------------------------------------------------------
extern "C" void kernel_launch(void* const* d_in, const int* in_sizes, int n_in,
                              void* d_out, int out_size) {
    const float* x        = (const float*)d_in[0];
    const int* edge_index = (const int*)d_in[1];   // [2, E]: src then dst
    const int* etype      = (const int*)d_in[2];
    const float* rgcn_w   = (const float*)d_in[3]; // [R, G, H1] == [1024,128]
    const float* rgcn_root= (const float*)d_in[4];
    const float* rgcn_b   = (const float*)d_in[5];
    const float* Wq = (const float*)d_in[6];  const float* bq = (const float*)d_in[7];
    const float* Wk = (const float*)d_in[8];  const float* bk = (const float*)d_in[9];
    const float* Wv = (const float*)d_in[10]; const float* bv = (const float*)d_in[11];
    const float* Ws = (const float*)d_in[12]; const float* bs = (const float*)d_in[13];
    float* out = (float*)d_out;

    const int* src = edge_index;
    const int* dst = edge_index + EE;

    // launch 0: zero everything
    {
        size_t n4 = ((size_t)NN * KAGG + 3) / 4;
        zero_kernel<<<(int)((n4 + 255) / 256), 256>>>();
    }
    // launch 1: per-(dst,rel) counts
    count_kernel<<<(EE + 255) / 256, 256>>>(dst, etype);
    // launch 2: RGCN scatter
    scatter_rgcn_kernel<<<(EE + 7) / 8, 256>>>(src, dst, etype, x);
    // launch 3 (ncu capture slot): big GEMM, BM=64 -> grid 313
    gemm_h_kernel<<<(NN + 63) / 64, 256>>>(x, rgcn_w, rgcn_root, rgcn_b);
    // launch 4: q,k,v,skip in one grid
    dim3 gq((NN + 63) / 64, 4);
    gemm_qkvs_kernel<<<gq, 256>>>(Wq, bq, Wk, bk, Wv, bv, Ws, bs, out);
    // launch 5: fused score+exp+den
    score_exp_kernel<<<(EE + 7) / 8, 256>>>(src, dst);
    // launch 6: alpha*v scatter onto skip
    scatter_v_kernel<<<(EE + 7) / 8, 256>>>(src, dst, out);
    // launch 7: final relu
    relu_kernel<<<(NN * H2 + 255) / 256, 256>>>(out, NN * H2);
}

// round 7
// speedup vs baseline: 1.3378x; 1.3378x over previous
#include <cuda_runtime.h>
#include <cuda_bf16.h>
#include <mma.h>
#include <math.h>
#include <stdint.h>

using namespace nvcuda;

// Problem constants
#define NN 20000
#define NPAD 20096            // 157 * 128, padded M so the GEMM needs no bounds checks
#define EE 640000
#define GG 128
#define RR 8
#define KSPLIT 384            // [hi | hi | lo] split-K
#define NOUT1 1152            // 8 relations * 128 + root 128
#define NOUT2 512             // q,k,v,skip

// ---------------- scratch (device globals; device-code use only) -----------
__device__ float g_y[(size_t)NPAD * NOUT1];              // ~92 MB
__device__ float g_hacc[NN * GG];                        // 10 MB
__device__ __nv_bfloat16 g_split[(size_t)NPAD * KSPLIT]; // A' (x, later h)
__device__ __nv_bfloat16 g_b1[(size_t)NOUT1 * KSPLIT];
__device__ __nv_bfloat16 g_b2[(size_t)NOUT2 * KSPLIT];
__device__ float g_q[(size_t)NPAD * GG];
__device__ float g_k[(size_t)NPAD * GG];
__device__ float g_v[(size_t)NPAD * GG];
__device__ float g_s[(size_t)NPAD * GG];
__device__ float g_cnt[NN * RR];
__device__ float g_e[EE];
__device__ float g_den[NN];

// ---------------- zero kernel -----------------------------------------------
__global__ void zero_kernel(float* __restrict__ out) {
    int i = blockIdx.x * blockDim.x + threadIdx.x;
    if (i < NN * GG / 4) {
        *(float4*)&g_hacc[i * 4] = make_float4(0.f, 0.f, 0.f, 0.f);
        *(float4*)&out[i * 4]    = make_float4(0.f, 0.f, 0.f, 0.f);
    }
    if (i < NN * RR) g_cnt[i] = 0.f;
    if (i < NN) g_den[i] = 0.f;
}

__global__ void count_kernel(const int* __restrict__ dst,
                             const int* __restrict__ etype) {
    int e = blockIdx.x * blockDim.x + threadIdx.x;
    if (e >= EE) return;
    atomicAdd(&g_cnt[dst[e] * RR + etype[e]], 1.0f);
}

// ---------------- split packing ---------------------------------------------
__device__ __forceinline__ void split_write(__nv_bfloat16* row, int k, float v) {
    __nv_bfloat16 hi = __float2bfloat16(v);
    __nv_bfloat16 lo = __float2bfloat16(v - __bfloat162float(hi));
    row[k] = hi; row[GG + k] = hi; row[2 * GG + k] = lo;   // A-style [hi|hi|lo]
}
__device__ __forceinline__ void split_write_b(__nv_bfloat16* row, int k, float v) {
    __nv_bfloat16 hi = __float2bfloat16(v);
    __nv_bfloat16 lo = __float2bfloat16(v - __bfloat162float(hi));
    row[k] = hi; row[GG + k] = lo; row[2 * GG + k] = hi;   // B-style [hi|lo|hi]
}

__global__ void pack_b1_kernel(const float* __restrict__ rgcn_w,
                               const float* __restrict__ root) {
    int i = blockIdx.x * blockDim.x + threadIdx.x;
    if (i >= NOUT1 * GG) return;
    int np = i >> 7, k = i & 127;
    float v;
    if (np < 1024) {
        int r = np >> 7, n = np & 127;
        v = rgcn_w[r * 16384 + k * 128 + n];
    } else {
        v = root[k * 128 + (np - 1024)];
    }
    split_write_b(&g_b1[(size_t)np * KSPLIT], k, v);
}

__global__ void pack_b2_kernel(const float* __restrict__ Wq,
                               const float* __restrict__ Wk,
                               const float* __restrict__ Wv,
                               const float* __restrict__ Ws) {
    int i = blockIdx.x * blockDim.x + threadIdx.x;
    if (i >= NOUT2 * GG) return;
    int np = i >> 7, k = i & 127;
    int sel = np >> 7, n = np & 127;
    const float* W = (sel == 0) ? Wq : (sel == 1) ? Wk : (sel == 2) ? Wv : Ws;
    split_write_b(&g_b2[(size_t)np * KSPLIT], k, W[k * 128 + n]);
}

__global__ void split_x_kernel(const float* __restrict__ x) {
    int i = blockIdx.x * blockDim.x + threadIdx.x;
    if (i >= NN * GG) return;
    int m = i >> 7, k = i & 127;
    split_write(&g_split[(size_t)m * KSPLIT], k, x[i]);
}

// ---------------- WMMA bf16 GEMM: C[M, Ntot] = A'[M,384] @ B'[Ntot,384]^T ---
// block tile 128x64, 8 warps (4x2) of 32x32, BK=32. No bounds checks (M padded).
__global__ void __launch_bounds__(256)
gemm_wmma_kernel(int mode) {
    __shared__ __nv_bfloat16 As[128][40];
    __shared__ __nv_bfloat16 Bs[64][40];
    int tid = threadIdx.x;
    int warp = tid >> 5;
    int wm = warp >> 1, wn = warp & 1;
    int row0 = blockIdx.x * 128;
    int n0 = blockIdx.y * 64;
    const __nv_bfloat16* Bgm = (mode == 0) ? g_b1 : g_b2;

    wmma::fragment<wmma::accumulator, 16, 16, 16, float> acc[2][2];
    #pragma unroll
    for (int i = 0; i < 2; i++)
        #pragma unroll
        for (int j = 0; j < 2; j++) wmma::fill_fragment(acc[i][j], 0.f);

    for (int k0 = 0; k0 < KSPLIT; k0 += 32) {
        // A tile: 128x32 bf16 = 512 uint4, 2 per thread
        #pragma unroll
        for (int i = 0; i < 2; i++) {
            int idx = tid + i * 256;
            int r = idx >> 2;
            int kc = (idx & 3) * 8;
            *(uint4*)&As[r][kc] =
                *(const uint4*)&g_split[(size_t)(row0 + r) * KSPLIT + k0 + kc];
        }
        // B tile: 64x32 bf16 = 256 uint4, 1 per thread
        {
            int r = tid >> 2;
            int kc = (tid & 3) * 8;
            *(uint4*)&Bs[r][kc] =
                *(const uint4*)&Bgm[(size_t)(n0 + r) * KSPLIT + k0 + kc];
        }
        __syncthreads();
        #pragma unroll
        for (int ks = 0; ks < 32; ks += 16) {
            wmma::fragment<wmma::matrix_a, 16, 16, 16, __nv_bfloat16, wmma::row_major> af[2];
            wmma::fragment<wmma::matrix_b, 16, 16, 16, __nv_bfloat16, wmma::col_major> bf[2];
            #pragma unroll
            for (int i = 0; i < 2; i++)
                wmma::load_matrix_sync(af[i], &As[wm * 32 + i * 16][ks], 40);
            #pragma unroll
            for (int j = 0; j < 2; j++)
                wmma::load_matrix_sync(bf[j], &Bs[wn * 32 + j * 16][ks], 40);
            #pragma unroll
            for (int i = 0; i < 2; i++)
                #pragma unroll
                for (int j = 0; j < 2; j++)
                    wmma::mma_sync(acc[i][j], af[i], bf[j], acc[i][j]);
        }
        __syncthreads();
    }

    if (mode == 0) {
        #pragma unroll
        for (int i = 0; i < 2; i++)
            #pragma unroll
            for (int j = 0; j < 2; j++)
                wmma::store_matrix_sync(
                    &g_y[(size_t)(row0 + wm * 32 + i * 16) * NOUT1
                         + n0 + wn * 32 + j * 16],
                    acc[i][j], NOUT1, wmma::mem_row_major);
    } else {
        int seg = n0 >> 7;
        float* Cb = (seg == 0) ? g_q : (seg == 1) ? g_k : (seg == 2) ? g_v : g_s;
        int col0 = (n0 & 127) + wn * 32;
        #pragma unroll
        for (int i = 0; i < 2; i++)
            #pragma unroll
            for (int j = 0; j < 2; j++)
                wmma::store_matrix_sync(
                    &Cb[(size_t)(row0 + wm * 32 + i * 16) * GG + col0 + j * 16],
                    acc[i][j], GG, wmma::mem_row_major);
    }
}

// ---------------- scatter: hacc[dst] += y[src, et*128..]/cnt ----------------
__global__ void scatter_y_kernel(const int* __restrict__ src,
                                 const int* __restrict__ dst,
                                 const int* __restrict__ etype) {
    int e = blockIdx.x * 8 + (threadIdx.x >> 5);
    if (e >= EE) return;
    int lane = threadIdx.x & 31;
    int s = src[e], d = dst[e], r = etype[e];
    float inv = 1.0f / fmaxf(g_cnt[d * RR + r], 1.0f);
    float4 yv = *(const float4*)&g_y[(size_t)s * NOUT1 + r * 128 + lane * 4];
    float* hd = &g_hacc[d * GG + lane * 4];
    atomicAdd(hd + 0, yv.x * inv);
    atomicAdd(hd + 1, yv.y * inv);
    atomicAdd(hd + 2, yv.z * inv);
    atomicAdd(hd + 3, yv.w * inv);
}

// h = relu(hacc + y_root + bias); write split(h) into g_split for GEMM2
__global__ void finalize_split_kernel(const float* __restrict__ bias) {
    int i = blockIdx.x * blockDim.x + threadIdx.x;
    if (i >= NN * GG) return;
    int m = i >> 7, c = i & 127;
    float h = g_hacc[i] + g_y[(size_t)m * NOUT1 + 1024 + c] + bias[c];
    h = fmaxf(h, 0.f);
    split_write(&g_split[(size_t)m * KSPLIT], c, h);
}

// ---------------- attention (biases folded in here) -------------------------
__global__ void score_exp_kernel(const int* __restrict__ src,
                                 const int* __restrict__ dst,
                                 const float* __restrict__ bq,
                                 const float* __restrict__ bk) {
    int e = blockIdx.x * 8 + (threadIdx.x >> 5);
    if (e >= EE) return;
    int lane = threadIdx.x & 31;
    int s = src[e], d = dst[e];
    float4 bqv = *(const float4*)&bq[lane * 4];
    float4 bkv = *(const float4*)&bk[lane * 4];
    float4 qv = *(const float4*)&g_q[(size_t)d * GG + lane * 4];
    float4 kv = *(const float4*)&g_k[(size_t)s * GG + lane * 4];
    float acc = (qv.x + bqv.x) * (kv.x + bkv.x)
              + (qv.y + bqv.y) * (kv.y + bkv.y)
              + (qv.z + bqv.z) * (kv.z + bkv.z)
              + (qv.w + bqv.w) * (kv.w + bkv.w);
    #pragma unroll
    for (int o = 16; o; o >>= 1) acc += __shfl_xor_sync(0xFFFFFFFFu, acc, o);
    if (lane == 0) {
        float ex = __expf(acc * 0.08838834764831845f);  // 1/sqrt(128)
        g_e[e] = ex;
        atomicAdd(&g_den[d], ex);
    }
}

__global__ void scatter_v_kernel(const int* __restrict__ src,
                                 const int* __restrict__ dst,
                                 const float* __restrict__ bv,
                                 float* __restrict__ out) {
    int e = blockIdx.x * 8 + (threadIdx.x >> 5);
    if (e >= EE) return;
    int lane = threadIdx.x & 31;
    int s = src[e], d = dst[e];
    float alpha = g_e[e] / fmaxf(g_den[d], 1e-16f);
    float4 bvv = *(const float4*)&bv[lane * 4];
    float4 vv = *(const float4*)&g_v[(size_t)s * GG + lane * 4];
    float* od = out + (size_t)d * GG + lane * 4;
    atomicAdd(od + 0, alpha * (vv.x + bvv.x));
    atomicAdd(od + 1, alpha * (vv.y + bvv.y));
    atomicAdd(od + 2, alpha * (vv.z + bvv.z));
    atomicAdd(od + 3, alpha * (vv.w + bvv.w));
}

// out = relu(attn_acc + skip + bs)
__global__ void final_kernel(float* __restrict__ out,
                             const float* __restrict__ bs) {
    int i = blockIdx.x * blockDim.x + threadIdx.x;
    if (i >= NN * GG) return;
    int m = i >> 7, c = i & 127;
    out[i] = fmaxf(out[i] + g_s[(size_t)m * GG + c] + bs[c], 0.f);
}

// ---------------------------------------------------------------------------
extern "C" void kernel_launch(void* const* d_in, const int* in_sizes, int n_in,
                              void* d_out, int out_size) {
    const float* x        = (const float*)d_in[0];
    const int* edge_index = (const int*)d_in[1];   // [2, E]: src then dst
    const int* etype      = (const int*)d_in[2];
    const float* rgcn_w   = (const float*)d_in[3];
    const float* rgcn_root= (const float*)d_in[4];
    const float* rgcn_b   = (const float*)d_in[5];
    const float* Wq = (const float*)d_in[6];  const float* bq = (const float*)d_in[7];
    const float* Wk = (const float*)d_in[8];  const float* bk = (const float*)d_in[9];
    const float* Wv = (const float*)d_in[10]; const float* bv = (const float*)d_in[11];
    const float* Ws = (const float*)d_in[12]; const float* bs = (const float*)d_in[13];
    float* out = (float*)d_out;

    const int* src = edge_index;
    const int* dst = edge_index + EE;

    // 0: zero hacc/cnt/den + out
    zero_kernel<<<(NN * GG / 4 + 255) / 256, 256>>>(out);
    // 1: per-(dst,rel) counts
    count_kernel<<<(EE + 255) / 256, 256>>>(dst, etype);
    // 2-4: weight packs + x split
    pack_b1_kernel<<<(NOUT1 * GG + 255) / 256, 256>>>(rgcn_w, rgcn_root);
    pack_b2_kernel<<<(NOUT2 * GG + 255) / 256, 256>>>(Wq, Wk, Wv, Ws);
    split_x_kernel<<<(NN * GG + 255) / 256, 256>>>(x);
    // 5 (ncu slot): y = x @ [W_r | root]  (tensor cores via WMMA)
    {
        dim3 g(NPAD / 128, NOUT1 / 64);   // 157 x 18
        gemm_wmma_kernel<<<g, 256>>>(0);
    }
    // 6: aggregate transformed features
    scatter_y_kernel<<<(EE + 7) / 8, 256>>>(src, dst, etype);
    // 7: h = relu(hacc + root-slice + bias), split into g_split
    finalize_split_kernel<<<(NN * GG + 255) / 256, 256>>>(rgcn_b);
    // 8: q,k,v,skip = h @ [Wq|Wk|Wv|Ws]
    {
        dim3 g(NPAD / 128, NOUT2 / 64);   // 157 x 8
        gemm_wmma_kernel<<<g, 256>>>(1);
    }
    // 9: fused score+exp+den (bq/bk folded in)
    score_exp_kernel<<<(EE + 7) / 8, 256>>>(src, dst, bq, bk);
    // 10: alpha*(v+bv) scatter into out
    scatter_v_kernel<<<(EE + 7) / 8, 256>>>(src, dst, bv, out);
    // 11: out = relu(out + skip + bs)
    final_kernel<<<(NN * GG + 255) / 256, 256>>>(out, bs);
}

// round 8
// speedup vs baseline: 1.9494x; 1.4572x over previous
#include <cuda_runtime.h>
#include <cuda_bf16.h>
#include <mma.h>
#include <math.h>
#include <stdint.h>

using namespace nvcuda;

// Problem constants
#define NN 20000
#define NPAD 20096            // 157 * 128 padded M
#define EE 640000
#define GG 128
#define RR 8
#define KSPLIT 384            // [hi | hi | lo] split-K
#define NOUT1 1152            // 8 relations * 128 + root
#define NOUT2 512             // q,k,v,skip

// ---------------- scratch (device globals; device-code use only) -----------
__device__ float g_y[(size_t)NPAD * 1024];               // 82 MB (relations only)
__device__ float g_hroot[(size_t)NPAD * GG];             // x @ root
__device__ float g_hacc[NN * GG];
__device__ __nv_bfloat16 g_split[(size_t)NPAD * KSPLIT]; // A' (x, later h)
__device__ __nv_bfloat16 g_b1[(size_t)NOUT1 * KSPLIT];
__device__ __nv_bfloat16 g_b2[(size_t)NOUT2 * KSPLIT];
__device__ float g_q[(size_t)NPAD * GG];
__device__ float g_k[(size_t)NPAD * GG];
__device__ float g_v[(size_t)NPAD * GG];
__device__ float g_s[(size_t)NPAD * GG];
__device__ float g_cnt[NN * RR];
__device__ float g_e[EE];
__device__ float g_den[NN];

// ---------------- vector reduction (sm_90+ PTX, arch-generic) ---------------
__device__ __forceinline__ void red_add_v4(float* p, float a, float b,
                                           float c, float d) {
    asm volatile("red.global.add.v4.f32 [%0], {%1, %2, %3, %4};"
                 :: "l"(p), "f"(a), "f"(b), "f"(c), "f"(d) : "memory");
}

// ---------------- zero / count ----------------------------------------------
__global__ void zero_kernel(float* __restrict__ out) {
    int i = blockIdx.x * blockDim.x + threadIdx.x;
    if (i < NN * GG / 4) {
        *(float4*)&g_hacc[i * 4] = make_float4(0.f, 0.f, 0.f, 0.f);
        *(float4*)&out[i * 4]    = make_float4(0.f, 0.f, 0.f, 0.f);
    }
    if (i < NN * RR) g_cnt[i] = 0.f;
    if (i < NN) g_den[i] = 0.f;
}

__global__ void count_kernel(const int* __restrict__ dst,
                             const int* __restrict__ etype) {
    int e = blockIdx.x * blockDim.x + threadIdx.x;
    if (e >= EE) return;
    atomicAdd(&g_cnt[dst[e] * RR + etype[e]], 1.0f);
}

// ---------------- split packing ---------------------------------------------
__device__ __forceinline__ void split_write(__nv_bfloat16* row, int k, float v) {
    __nv_bfloat16 hi = __float2bfloat16(v);
    __nv_bfloat16 lo = __float2bfloat16(v - __bfloat162float(hi));
    row[k] = hi; row[GG + k] = hi; row[2 * GG + k] = lo;   // A-style [hi|hi|lo]
}
__device__ __forceinline__ void split_write_b(__nv_bfloat16* row, int k, float v) {
    __nv_bfloat16 hi = __float2bfloat16(v);
    __nv_bfloat16 lo = __float2bfloat16(v - __bfloat162float(hi));
    row[k] = hi; row[GG + k] = lo; row[2 * GG + k] = hi;   // B-style [hi|lo|hi]
}

__global__ void pack_b1_kernel(const float* __restrict__ rgcn_w,
                               const float* __restrict__ root) {
    int i = blockIdx.x * blockDim.x + threadIdx.x;
    if (i >= NOUT1 * GG) return;
    int np = i >> 7, k = i & 127;
    float v;
    if (np < 1024) {
        int r = np >> 7, n = np & 127;
        v = rgcn_w[r * 16384 + k * 128 + n];
    } else {
        v = root[k * 128 + (np - 1024)];
    }
    split_write_b(&g_b1[(size_t)np * KSPLIT], k, v);
}

__global__ void pack_b2_kernel(const float* __restrict__ Wq,
                               const float* __restrict__ Wk,
                               const float* __restrict__ Wv,
                               const float* __restrict__ Ws) {
    int i = blockIdx.x * blockDim.x + threadIdx.x;
    if (i >= NOUT2 * GG) return;
    int np = i >> 7, k = i & 127;
    int sel = np >> 7, n = np & 127;
    const float* W = (sel == 0) ? Wq : (sel == 1) ? Wk : (sel == 2) ? Wv : Ws;
    split_write_b(&g_b2[(size_t)np * KSPLIT], k, W[k * 128 + n]);
}

__global__ void split_x_kernel(const float* __restrict__ x) {
    int i = blockIdx.x * blockDim.x + threadIdx.x;
    if (i >= NN * GG) return;
    int m = i >> 7, k = i & 127;
    split_write(&g_split[(size_t)m * KSPLIT], k, x[i]);
}

// ---------------- WMMA bf16 GEMM: 128x128 block tile, BK=32 -----------------
// 8 warps as 4x2; each warp 32x64 (acc 2x4 of 16x16). M padded, no bounds checks.
__global__ void __launch_bounds__(256)
gemm_wmma_kernel(int mode) {
    __shared__ __nv_bfloat16 As[128][40];
    __shared__ __nv_bfloat16 Bs[128][40];
    int tid = threadIdx.x;
    int warp = tid >> 5;
    int wm = warp >> 1, wn = warp & 1;
    int row0 = blockIdx.x * 128;
    int n0 = blockIdx.y * 128;
    const __nv_bfloat16* Bgm = (mode == 0) ? g_b1 : g_b2;

    wmma::fragment<wmma::accumulator, 16, 16, 16, float> acc[2][4];
    #pragma unroll
    for (int i = 0; i < 2; i++)
        #pragma unroll
        for (int j = 0; j < 4; j++) wmma::fill_fragment(acc[i][j], 0.f);

    for (int k0 = 0; k0 < KSPLIT; k0 += 32) {
        #pragma unroll
        for (int i = 0; i < 2; i++) {
            int idx = tid + i * 256;
            int r = idx >> 2;
            int kc = (idx & 3) * 8;
            *(uint4*)&As[r][kc] =
                *(const uint4*)&g_split[(size_t)(row0 + r) * KSPLIT + k0 + kc];
            *(uint4*)&Bs[r][kc] =
                *(const uint4*)&Bgm[(size_t)(n0 + r) * KSPLIT + k0 + kc];
        }
        __syncthreads();
        #pragma unroll
        for (int ks = 0; ks < 32; ks += 16) {
            wmma::fragment<wmma::matrix_a, 16, 16, 16, __nv_bfloat16, wmma::row_major> af[2];
            wmma::fragment<wmma::matrix_b, 16, 16, 16, __nv_bfloat16, wmma::col_major> bf[4];
            #pragma unroll
            for (int i = 0; i < 2; i++)
                wmma::load_matrix_sync(af[i], &As[wm * 32 + i * 16][ks], 40);
            #pragma unroll
            for (int j = 0; j < 4; j++)
                wmma::load_matrix_sync(bf[j], &Bs[wn * 64 + j * 16][ks], 40);
            #pragma unroll
            for (int i = 0; i < 2; i++)
                #pragma unroll
                for (int j = 0; j < 4; j++)
                    wmma::mma_sync(acc[i][j], af[i], bf[j], acc[i][j]);
        }
        __syncthreads();
    }

    if (mode == 0) {
        if (blockIdx.y < 8) {
            #pragma unroll
            for (int i = 0; i < 2; i++)
                #pragma unroll
                for (int j = 0; j < 4; j++)
                    wmma::store_matrix_sync(
                        &g_y[(size_t)(row0 + wm * 32 + i * 16) * 1024
                             + n0 + wn * 64 + j * 16],
                        acc[i][j], 1024, wmma::mem_row_major);
        } else {
            #pragma unroll
            for (int i = 0; i < 2; i++)
                #pragma unroll
                for (int j = 0; j < 4; j++)
                    wmma::store_matrix_sync(
                        &g_hroot[(size_t)(row0 + wm * 32 + i * 16) * GG
                                 + wn * 64 + j * 16],
                        acc[i][j], GG, wmma::mem_row_major);
        }
    } else {
        int seg = blockIdx.y;
        float* Cb = (seg == 0) ? g_q : (seg == 1) ? g_k : (seg == 2) ? g_v : g_s;
        #pragma unroll
        for (int i = 0; i < 2; i++)
            #pragma unroll
            for (int j = 0; j < 4; j++)
                wmma::store_matrix_sync(
                    &Cb[(size_t)(row0 + wm * 32 + i * 16) * GG + wn * 64 + j * 16],
                    acc[i][j], GG, wmma::mem_row_major);
    }
}

// ---------------- scatter: hacc[dst] += y[src, et*128..]/cnt ----------------
__global__ void scatter_y_kernel(const int* __restrict__ src,
                                 const int* __restrict__ dst,
                                 const int* __restrict__ etype) {
    int e = blockIdx.x * 8 + (threadIdx.x >> 5);
    if (e >= EE) return;
    int lane = threadIdx.x & 31;
    int s = src[e], d = dst[e], r = etype[e];
    float inv = 1.0f / fmaxf(g_cnt[d * RR + r], 1.0f);
    float4 yv = *(const float4*)&g_y[(size_t)s * 1024 + r * 128 + lane * 4];
    red_add_v4(&g_hacc[d * GG + lane * 4],
               yv.x * inv, yv.y * inv, yv.z * inv, yv.w * inv);
}

// h = relu(hacc + hroot + bias); write split(h) into g_split for GEMM2
__global__ void finalize_split_kernel(const float* __restrict__ bias) {
    int i = blockIdx.x * blockDim.x + threadIdx.x;
    if (i >= NN * GG) return;
    int m = i >> 7, c = i & 127;
    float h = g_hacc[i] + g_hroot[(size_t)m * GG + c] + bias[c];
    h = fmaxf(h, 0.f);
    split_write(&g_split[(size_t)m * KSPLIT], c, h);
}

// ---------------- attention (biases folded in here) -------------------------
__global__ void score_exp_kernel(const int* __restrict__ src,
                                 const int* __restrict__ dst,
                                 const float* __restrict__ bq,
                                 const float* __restrict__ bk) {
    int e = blockIdx.x * 8 + (threadIdx.x >> 5);
    if (e >= EE) return;
    int lane = threadIdx.x & 31;
    int s = src[e], d = dst[e];
    float4 bqv = *(const float4*)&bq[lane * 4];
    float4 bkv = *(const float4*)&bk[lane * 4];
    float4 qv = *(const float4*)&g_q[(size_t)d * GG + lane * 4];
    float4 kv = *(const float4*)&g_k[(size_t)s * GG + lane * 4];
    float acc = (qv.x + bqv.x) * (kv.x + bkv.x)
              + (qv.y + bqv.y) * (kv.y + bkv.y)
              + (qv.z + bqv.z) * (kv.z + bkv.z)
              + (qv.w + bqv.w) * (kv.w + bkv.w);
    #pragma unroll
    for (int o = 16; o; o >>= 1) acc += __shfl_xor_sync(0xFFFFFFFFu, acc, o);
    if (lane == 0) {
        float ex = __expf(acc * 0.08838834764831845f);  // 1/sqrt(128)
        g_e[e] = ex;
        atomicAdd(&g_den[d], ex);
    }
}

__global__ void scatter_v_kernel(const int* __restrict__ src,
                                 const int* __restrict__ dst,
                                 const float* __restrict__ bv,
                                 float* __restrict__ out) {
    int e = blockIdx.x * 8 + (threadIdx.x >> 5);
    if (e >= EE) return;
    int lane = threadIdx.x & 31;
    int s = src[e], d = dst[e];
    float alpha = g_e[e] / fmaxf(g_den[d], 1e-16f);
    float4 bvv = *(const float4*)&bv[lane * 4];
    float4 vv = *(const float4*)&g_v[(size_t)s * GG + lane * 4];
    red_add_v4(out + (size_t)d * GG + lane * 4,
               alpha * (vv.x + bvv.x), alpha * (vv.y + bvv.y),
               alpha * (vv.z + bvv.z), alpha * (vv.w + bvv.w));
}

// out = relu(attn_acc + skip + bs)
__global__ void final_kernel(float* __restrict__ out,
                             const float* __restrict__ bs) {
    int i = blockIdx.x * blockDim.x + threadIdx.x;
    if (i >= NN * GG) return;
    int m = i >> 7, c = i & 127;
    out[i] = fmaxf(out[i] + g_s[(size_t)m * GG + c] + bs[c], 0.f);
}

// ---------------------------------------------------------------------------
extern "C" void kernel_launch(void* const* d_in, const int* in_sizes, int n_in,
                              void* d_out, int out_size) {
    const float* x        = (const float*)d_in[0];
    const int* edge_index = (const int*)d_in[1];   // [2, E]: src then dst
    const int* etype      = (const int*)d_in[2];
    const float* rgcn_w   = (const float*)d_in[3];
    const float* rgcn_root= (const float*)d_in[4];
    const float* rgcn_b   = (const float*)d_in[5];
    const float* Wq = (const float*)d_in[6];  const float* bq = (const float*)d_in[7];
    const float* Wk = (const float*)d_in[8];  const float* bk = (const float*)d_in[9];
    const float* Wv = (const float*)d_in[10]; const float* bv = (const float*)d_in[11];
    const float* Ws = (const float*)d_in[12]; const float* bs = (const float*)d_in[13];
    float* out = (float*)d_out;

    const int* src = edge_index;
    const int* dst = edge_index + EE;

    // 0-2: packs + split (independent of zero/count)
    pack_b1_kernel<<<(NOUT1 * GG + 255) / 256, 256>>>(rgcn_w, rgcn_root);
    pack_b2_kernel<<<(NOUT2 * GG + 255) / 256, 256>>>(Wq, Wk, Wv, Ws);
    split_x_kernel<<<(NN * GG + 255) / 256, 256>>>(x);
    // 3 (ncu capture slot): y = x @ [W_r | root]
    {
        dim3 g(NPAD / 128, 9);
        gemm_wmma_kernel<<<g, 256>>>(0);
    }
    // 4: zero hacc/out/cnt/den
    zero_kernel<<<(NN * GG / 4 + 255) / 256, 256>>>(out);
    // 5: per-(dst,rel) counts
    count_kernel<<<(EE + 255) / 256, 256>>>(dst, etype);
    // 6: aggregate transformed features (vector reds)
    scatter_y_kernel<<<(EE + 7) / 8, 256>>>(src, dst, etype);
    // 7: h = relu(hacc + hroot + bias), split into g_split
    finalize_split_kernel<<<(NN * GG + 255) / 256, 256>>>(rgcn_b);
    // 8: q,k,v,skip = h @ [Wq|Wk|Wv|Ws]
    {
        dim3 g(NPAD / 128, 4);
        gemm_wmma_kernel<<<g, 256>>>(1);
    }
    // 9: fused score+exp+den (bq/bk folded in)
    score_exp_kernel<<<(EE + 7) / 8, 256>>>(src, dst, bq, bk);
    // 10: alpha*(v+bv) scatter into out (vector reds)
    scatter_v_kernel<<<(EE + 7) / 8, 256>>>(src, dst, bv, out);
    // 11: out = relu(out + skip + bs)
    final_kernel<<<(NN * GG + 255) / 256, 256>>>(out, bs);
}